// round 5
// baseline (speedup 1.0000x reference)
#include <cuda_runtime.h>
#include <cuda_fp16.h>
#include <cstdint>

#define NN 100000
#define NE 1600000

// ---------------- device scratch (no allocation APIs allowed) ----------------
__device__ __align__(16) float g_X[NN * 64];      // node features (post-relu)
__device__ __align__(16) float g_D[NN * 128];     // dst-side proj [f|s] fp32, bias folded
__device__ __align__(16) uint2 g_Spk[NN * 32];    // src-side proj packed fp16:
                                                  //  lane l: {f2l,f2l+1,s2l,s2l+1}
__device__ __align__(16) float g_E8[NE * 8];      // permuted edge feats, stride 8 (e0..e4)
__device__ int g_deg[NN];                         // degree / scatter cursor
__device__ int g_off[NN + 1];                     // CSR offsets (by dst)
__device__ int g_srcp[NE];                        // src node id, permuted (sorted by dst)
__device__ int g_rank[NE];                        // edge e -> permuted slot

__device__ __forceinline__ float sigm_t(float x) {
    float t;
    asm("tanh.approx.f32 %0, %1;" : "=f"(t) : "f"(0.5f * x));
    return fmaf(0.5f, t, 0.5f);
}
__device__ __forceinline__ float softplus_f(float x) {
    return fmaxf(x, 0.0f) + __logf(1.0f + __expf(-fabsf(x)));
}

// ---------------------------------------------------------------------------
// CSR build
// ---------------------------------------------------------------------------
__global__ void k_zero_deg() {
    int i = blockIdx.x * 256 + threadIdx.x;
    if (i < NN) g_deg[i] = 0;
}

__global__ void k_hist(const int* __restrict__ ei) {
    int e = blockIdx.x * 256 + threadIdx.x;
    if (e < NE) atomicAdd(&g_deg[ei[NE + e]], 1);
}

// single-block exclusive scan: 1024 threads, 98 elems/thread
__global__ __launch_bounds__(1024) void k_scan() {
    const int C = 98;
    int t = threadIdx.x;
    int beg = t * C;
    int end = min(beg + C, NN);
    int sum = 0;
    for (int i = beg; i < end; i++) sum += g_deg[i];

    __shared__ int wsum[32];
    int lane = t & 31, wid = t >> 5;
    int v = sum;
#pragma unroll
    for (int o = 1; o < 32; o <<= 1) {
        int u = __shfl_up_sync(0xffffffffu, v, o);
        if (lane >= o) v += u;
    }
    if (lane == 31) wsum[wid] = v;
    __syncthreads();
    if (wid == 0) {
        int w = wsum[lane];
#pragma unroll
        for (int o = 1; o < 32; o <<= 1) {
            int u = __shfl_up_sync(0xffffffffu, w, o);
            if (lane >= o) w += u;
        }
        wsum[lane] = w;
    }
    __syncthreads();
    int excl = v - sum + (wid > 0 ? wsum[wid - 1] : 0);
    int run = excl;
    for (int i = beg; i < end; i++) {
        g_off[i] = run;
        run += g_deg[i];
    }
    if (t == 1023) g_off[NN] = run;
}

__global__ void k_scatter(const int* __restrict__ ei) {
    int e = blockIdx.x * 256 + threadIdx.x;
    if (e >= NE) return;
    int d = ei[NE + e];
    int pos = g_off[d] + atomicAdd(&g_deg[d], 1);
    g_srcp[pos] = ei[e];
    g_rank[e] = pos;
}

// ---------------------------------------------------------------------------
// K1: X = relu(h @ lin0_w + lin0_b)
// ---------------------------------------------------------------------------
__global__ __launch_bounds__(256) void k_lin0(const float* __restrict__ h,
                                              const float* __restrict__ w,
                                              const float* __restrict__ b) {
    __shared__ float Ws[64 * 64];
    __shared__ float Bs[64];
    __shared__ float Xs[8][64];
    const int t = threadIdx.x;
    for (int i = t; i < 64 * 64; i += 256) Ws[i] = w[i];
    if (t < 64) Bs[t] = b[t];

    const int base = blockIdx.x * 64;
    const int c = t & 63;
    const int r0 = t >> 6;

    for (int j = 0; j < 64; j += 8) {
        __syncthreads();
        for (int i = t; i < 8 * 64; i += 256) {
            int n = base + j + (i >> 6);
            Xs[i >> 6][i & 63] = (n < NN) ? h[(size_t)n * 64 + (i & 63)] : 0.0f;
        }
        __syncthreads();
#pragma unroll
        for (int rr = 0; rr < 2; rr++) {
            int row = r0 + rr * 4;
            int n = base + j + row;
            if (n < NN) {
                float acc = Bs[c];
#pragma unroll
                for (int k = 0; k < 64; k++)
                    acc = fmaf(Xs[row][k], Ws[k * 64 + c], acc);
                g_X[(size_t)n * 64 + c] = fmaxf(acc, 0.0f);
            }
        }
    }
}

// ---------------------------------------------------------------------------
// K2: permuted edge feats, stride 8: g_E8[rank*8 + 0..4] = relu(ea @ w + b)
// ---------------------------------------------------------------------------
__global__ __launch_bounds__(256) void k_edgefeat(const float* __restrict__ ea,
                                                  const float* __restrict__ w,
                                                  const float* __restrict__ b) {
    int e = blockIdx.x * 256 + threadIdx.x;
    if (e >= NE) return;
    float a0 = ea[(size_t)e * 5 + 0], a1 = ea[(size_t)e * 5 + 1],
          a2 = ea[(size_t)e * 5 + 2], a3 = ea[(size_t)e * 5 + 3],
          a4 = ea[(size_t)e * 5 + 4];
    size_t o = (size_t)g_rank[e] * 8;
#pragma unroll
    for (int c = 0; c < 5; c++) {
        float acc = b[c];
        acc = fmaf(a0, w[0 * 5 + c], acc);
        acc = fmaf(a1, w[1 * 5 + c], acc);
        acc = fmaf(a2, w[2 * 5 + c], acc);
        acc = fmaf(a3, w[3 * 5 + c], acc);
        acc = fmaf(a4, w[4 * 5 + c], acc);
        g_E8[o + c] = fmaxf(acc, 0.0f);
    }
}

// ---------------------------------------------------------------------------
// K3: node projections. H=0 -> D fp32 (bias folded); H=1 -> packed fp16 S.
// 128x128 tile, 8x8 per thread.
// ---------------------------------------------------------------------------
__global__ __launch_bounds__(256) void k_proj(const float* __restrict__ wf,
                                              const float* __restrict__ ws,
                                              const float* __restrict__ bf,
                                              const float* __restrict__ bs) {
    __shared__ float Xs[32 * 129];
    __shared__ float Wsm[32 * 128];
    const int t = threadIdx.x;
    const int tx = t & 15, ty = t >> 4;
    const int H = blockIdx.y;
    const int base = blockIdx.x * 128;

    float acc[8][8];
#pragma unroll
    for (int i = 0; i < 8; i++)
#pragma unroll
        for (int j = 0; j < 8; j++) acc[i][j] = 0.0f;

    for (int ks = 0; ks < 64; ks += 32) {
        __syncthreads();
#pragma unroll
        for (int r = 0; r < 16; r++) {
            int idx = t + 256 * r;
            int n = idx >> 5;
            int k = idx & 31;
            int gn = base + n;
            Xs[k * 129 + n] = (gn < NN) ? g_X[(size_t)gn * 64 + ks + k] : 0.0f;
        }
#pragma unroll
        for (int r = 0; r < 16; r++) {
            int idx = t + 256 * r;
            int k = idx >> 7;
            int c = idx & 127;
            int grow = H * 64 + ks + k;
            Wsm[k * 128 + c] = (c < 64) ? wf[grow * 64 + c] : ws[grow * 64 + (c - 64)];
        }
        __syncthreads();
#pragma unroll
        for (int k = 0; k < 32; k++) {
            float xr[8], wr[8];
#pragma unroll
            for (int i = 0; i < 8; i++) xr[i] = Xs[k * 129 + i * 16 + ty];
#pragma unroll
            for (int j = 0; j < 8; j++) wr[j] = Wsm[k * 128 + j * 16 + tx];
#pragma unroll
            for (int i = 0; i < 8; i++)
#pragma unroll
                for (int j = 0; j < 8; j++)
                    acc[i][j] = fmaf(xr[i], wr[j], acc[i][j]);
        }
    }

    if (H == 0) {
#pragma unroll
        for (int i = 0; i < 8; i++) {
            int n = base + i * 16 + ty;
            if (n >= NN) continue;
#pragma unroll
            for (int j = 0; j < 8; j++) {
                int c = j * 16 + tx;
                float v = acc[i][j] + ((c < 64) ? bf[c] : bs[c - 64]);
                g_D[(size_t)n * 128 + c] = v;
            }
        }
    } else {
        __half* outp = reinterpret_cast<__half*>(g_Spk);
#pragma unroll
        for (int i = 0; i < 8; i++) {
            int n = base + i * 16 + ty;
            if (n >= NN) continue;
#pragma unroll
            for (int j = 0; j < 8; j++) {
                int c = j * 16 + tx;
                int cc = (c < 64) ? c : c - 64;
                int posh = 4 * (cc >> 1) + ((c < 64) ? 0 : 2) + (cc & 1);
                outp[(size_t)n * 128 + posh] = __float2half(acc[i][j]);
            }
        }
    }
}

// ---------------------------------------------------------------------------
// K4: CSR aggregation. One WARP per dst node; lane l owns channels 2l, 2l+1.
// S gathered as ONE 8-byte packed-fp16 load per lane per edge. srcp ids
// preloaded per-chunk and shuffle-broadcast. Fused residual + relu epilogue.
// ---------------------------------------------------------------------------
__global__ __launch_bounds__(256) void k_edge_csr(const float* __restrict__ wef,
                                                  const float* __restrict__ wes,
                                                  float* __restrict__ out,
                                                  int final_) {
    int gw = (blockIdx.x * 256 + threadIdx.x) >> 5;
    int l = threadIdx.x & 31;
    if (gw >= NN) return;
    const int n = gw;

    float wf0[5], wf1[5], ws0[5], ws1[5];
#pragma unroll
    for (int k = 0; k < 5; k++) {
        wf0[k] = wef[k * 64 + 2 * l];
        wf1[k] = wef[k * 64 + 2 * l + 1];
        ws0[k] = wes[k * 64 + 2 * l];
        ws1[k] = wes[k * 64 + 2 * l + 1];
    }

    const float2* D2 = reinterpret_cast<const float2*>(g_D + (size_t)n * 128);
    float2 Df = D2[l];        // f channels 2l,2l+1 (bias folded)
    float2 Dsv = D2[32 + l];  // s channels

    float m0 = 0.0f, m1 = 0.0f;
    const int beg = __ldg(&g_off[n]), end = __ldg(&g_off[n + 1]);

    for (int cb = beg; cb < end; cb += 32) {
        int cnt = min(32, end - cb);
        int myS = (cb + l < end) ? __ldg(&g_srcp[cb + l]) : 0;
#pragma unroll 4
        for (int j = 0; j < cnt; j++) {
            int s = __shfl_sync(0xffffffffu, myS, j);
            int k = cb + j;
            const float4 ev = *reinterpret_cast<const float4*>(g_E8 + (size_t)k * 8);
            float e4v = g_E8[(size_t)k * 8 + 4];

            uint2 sp = __ldg(&g_Spk[(size_t)s * 32 + l]);
            float2 Sf = __half22float2(*reinterpret_cast<__half2*>(&sp.x));
            float2 Ssv = __half22float2(*reinterpret_cast<__half2*>(&sp.y));

            float zf0 = Df.x + Sf.x;
            zf0 = fmaf(ev.x, wf0[0], zf0); zf0 = fmaf(ev.y, wf0[1], zf0);
            zf0 = fmaf(ev.z, wf0[2], zf0); zf0 = fmaf(ev.w, wf0[3], zf0);
            zf0 = fmaf(e4v, wf0[4], zf0);
            float zf1 = Df.y + Sf.y;
            zf1 = fmaf(ev.x, wf1[0], zf1); zf1 = fmaf(ev.y, wf1[1], zf1);
            zf1 = fmaf(ev.z, wf1[2], zf1); zf1 = fmaf(ev.w, wf1[3], zf1);
            zf1 = fmaf(e4v, wf1[4], zf1);
            float zs0 = Dsv.x + Ssv.x;
            zs0 = fmaf(ev.x, ws0[0], zs0); zs0 = fmaf(ev.y, ws0[1], zs0);
            zs0 = fmaf(ev.z, ws0[2], zs0); zs0 = fmaf(ev.w, ws0[3], zs0);
            zs0 = fmaf(e4v, ws0[4], zs0);
            float zs1 = Dsv.y + Ssv.y;
            zs1 = fmaf(ev.x, ws1[0], zs1); zs1 = fmaf(ev.y, ws1[1], zs1);
            zs1 = fmaf(ev.z, ws1[2], zs1); zs1 = fmaf(ev.w, ws1[3], zs1);
            zs1 = fmaf(e4v, ws1[4], zs1);

            m0 += sigm_t(zf0) * softplus_f(zs0);
            m1 += sigm_t(zf1) * softplus_f(zs1);
        }
    }

    float2 x = *reinterpret_cast<const float2*>(g_X + (size_t)n * 64 + 2 * l);
    float2 r = make_float2(fmaxf(x.x + m0, 0.0f), fmaxf(x.y + m1, 0.0f));
    if (final_) {
        *reinterpret_cast<float2*>(out + (size_t)n * 64 + 2 * l) = r;
    } else {
        *reinterpret_cast<float2*>(g_X + (size_t)n * 64 + 2 * l) = r;
    }
}

// ---------------------------------------------------------------------------
// Launch. Inputs: h, edge_index, edge_weight, edge_attr, data,
// lin0_w, lin0_b, short_w, short_b, conv_f_w, conv_f_b, conv_s_w, conv_s_b
// ---------------------------------------------------------------------------
extern "C" void kernel_launch(void* const* d_in, const int* in_sizes, int n_in,
                              void* d_out, int out_size) {
    int o = (n_in >= 13) ? 0 : -1;

    const float* h = (const float*)d_in[0];
    const int* ei = (const int*)d_in[1];  // int32 [2, NE]
    const float* ea = (const float*)d_in[3];
    const float* lin0_w = (const float*)d_in[5 + o];
    const float* lin0_b = (const float*)d_in[6 + o];
    const float* short_w = (const float*)d_in[7 + o];
    const float* short_b = (const float*)d_in[8 + o];
    const float* cfw = (const float*)d_in[9 + o];   // [2,133,64]
    const float* cfb = (const float*)d_in[10 + o];  // [2,64]
    const float* csw = (const float*)d_in[11 + o];
    const float* csb = (const float*)d_in[12 + o];
    float* out = (float*)d_out;

    const int NB = (NN + 255) / 256;
    const int EB = (NE + 255) / 256;

    // CSR build (dst-sorted), shared by both convs
    k_zero_deg<<<NB, 256>>>();
    k_hist<<<EB, 256>>>(ei);
    k_scan<<<1, 1024>>>();
    k_zero_deg<<<NB, 256>>>();
    k_scatter<<<EB, 256>>>(ei);

    k_lin0<<<(NN + 63) / 64, 256>>>(h, lin0_w, lin0_b);
    k_edgefeat<<<EB, 256>>>(ea, short_w, short_b);

    for (int i = 0; i < 2; i++) {
        const float* wf = cfw + (size_t)i * 133 * 64;
        const float* ws = csw + (size_t)i * 133 * 64;
        dim3 pg((NN + 127) / 128, 2);
        k_proj<<<pg, 256>>>(wf, ws, cfb + i * 64, csb + i * 64);
        k_edge_csr<<<(NN * 32 + 255) / 256, 256>>>(wf + 128 * 64, ws + 128 * 64,
                                                   out, i == 1 ? 1 : 0);
    }
}

// round 6
// speedup vs baseline: 1.2235x; 1.2235x over previous
#include <cuda_runtime.h>
#include <cuda_fp16.h>
#include <cstdint>
#include <cstring>

#define NN 100000
#define NE 1600000
#define LB 1563          // lin0 blocks in fused prep: ceil(100000/64)
#define EBF 6250         // edgefeat blocks: 1600000/256

// ---------------- device scratch (no allocation APIs allowed) ----------------
__device__ __align__(16) float g_X[NN * 64];     // node features fp32 (post-relu)
__device__ __align__(16) uint2 g_Dpk[NN * 32];   // dst proj packed fp16 (bias folded)
__device__ __align__(16) uint2 g_Spk[NN * 32];   // src proj packed fp16
__device__ __align__(16) unsigned g_E32[NE * 8]; // edge feats: 5 duplicated half2 + pad (32B)
__device__ int g_deg[NN];                        // statically zero; hist fills, scatter drains
__device__ int g_off[NN + 1];                    // CSR offsets (by dst)
__device__ int g_srcp[NE];                       // src id, permuted (sorted by dst)
__device__ int g_rank[NE];                       // edge e -> permuted slot

__device__ __forceinline__ __half2 u2h(unsigned u) {
    __half2 h;
    memcpy(&h, &u, 4);
    return h;
}
__device__ __forceinline__ unsigned h2u(__half2 h) {
    unsigned u;
    memcpy(&u, &h, 4);
    return u;
}
__device__ __forceinline__ __half2 tanh_h2(__half2 x) {
    unsigned r, xu = h2u(x);
    asm("tanh.approx.f16x2 %0, %1;" : "=r"(r) : "r"(xu));
    return u2h(r);
}
__device__ __forceinline__ float softplus_f(float x) {
    return fmaxf(x, 0.0f) + __logf(1.0f + __expf(-fabsf(x)));
}

// ---------------------------------------------------------------------------
// CSR build (g_deg starts at 0: static init on first call, drained by scatter
// on every call -> replay-invariant)
// ---------------------------------------------------------------------------
__global__ void k_hist(const int* __restrict__ ei) {
    int e = blockIdx.x * 256 + threadIdx.x;
    if (e < NE) atomicAdd(&g_deg[ei[NE + e]], 1);
}

__global__ __launch_bounds__(1024) void k_scan() {
    const int C = 98;
    int t = threadIdx.x;
    int beg = t * C;
    int end = min(beg + C, NN);
    int sum = 0;
    for (int i = beg; i < end; i++) sum += g_deg[i];

    __shared__ int wsum[32];
    int lane = t & 31, wid = t >> 5;
    int v = sum;
#pragma unroll
    for (int o = 1; o < 32; o <<= 1) {
        int u = __shfl_up_sync(0xffffffffu, v, o);
        if (lane >= o) v += u;
    }
    if (lane == 31) wsum[wid] = v;
    __syncthreads();
    if (wid == 0) {
        int w = wsum[lane];
#pragma unroll
        for (int o = 1; o < 32; o <<= 1) {
            int u = __shfl_up_sync(0xffffffffu, w, o);
            if (lane >= o) w += u;
        }
        wsum[lane] = w;
    }
    __syncthreads();
    int excl = v - sum + (wid > 0 ? wsum[wid - 1] : 0);
    int run = excl;
    for (int i = beg; i < end; i++) {
        g_off[i] = run;
        run += g_deg[i];
    }
    if (t == 1023) g_off[NN] = run;
}

__global__ void k_scatter(const int* __restrict__ ei) {
    int e = blockIdx.x * 256 + threadIdx.x;
    if (e >= NE) return;
    int d = ei[NE + e];
    int old = atomicSub(&g_deg[d], 1);   // drains deg back to 0 for next call
    int pos = g_off[d] + old - 1;
    g_srcp[pos] = ei[e];
    g_rank[e] = pos;
}

// ---------------------------------------------------------------------------
// K_prep (fused): blocks [0,LB) -> X = relu(h@lin0_w+b);
//                 blocks [LB,LB+EBF) -> permuted duplicated-fp16 edge feats.
// ---------------------------------------------------------------------------
__global__ __launch_bounds__(256) void k_prep(const float* __restrict__ h,
                                              const float* __restrict__ w,
                                              const float* __restrict__ b,
                                              const float* __restrict__ ea,
                                              const float* __restrict__ sw,
                                              const float* __restrict__ sb) {
    const int t = threadIdx.x;
    if (blockIdx.x < LB) {
        __shared__ float Ws[64 * 64];
        __shared__ float Bs[64];
        __shared__ float Xs[8][64];
        for (int i = t; i < 64 * 64; i += 256) Ws[i] = w[i];
        if (t < 64) Bs[t] = b[t];

        const int base = blockIdx.x * 64;
        const int c = t & 63;
        const int r0 = t >> 6;

        for (int j = 0; j < 64; j += 8) {
            __syncthreads();
            for (int i = t; i < 8 * 64; i += 256) {
                int n = base + j + (i >> 6);
                Xs[i >> 6][i & 63] = (n < NN) ? h[(size_t)n * 64 + (i & 63)] : 0.0f;
            }
            __syncthreads();
#pragma unroll
            for (int rr = 0; rr < 2; rr++) {
                int row = r0 + rr * 4;
                int n = base + j + row;
                if (n < NN) {
                    float acc = Bs[c];
#pragma unroll
                    for (int k = 0; k < 64; k++)
                        acc = fmaf(Xs[row][k], Ws[k * 64 + c], acc);
                    g_X[(size_t)n * 64 + c] = fmaxf(acc, 0.0f);
                }
            }
        }
    } else {
        int e = (blockIdx.x - LB) * 256 + t;
        if (e >= NE) return;
        float a0 = ea[(size_t)e * 5 + 0], a1 = ea[(size_t)e * 5 + 1],
              a2 = ea[(size_t)e * 5 + 2], a3 = ea[(size_t)e * 5 + 3],
              a4 = ea[(size_t)e * 5 + 4];
        size_t o = (size_t)g_rank[e] * 8;
#pragma unroll
        for (int c = 0; c < 5; c++) {
            float acc = sb[c];
            acc = fmaf(a0, sw[0 * 5 + c], acc);
            acc = fmaf(a1, sw[1 * 5 + c], acc);
            acc = fmaf(a2, sw[2 * 5 + c], acc);
            acc = fmaf(a3, sw[3 * 5 + c], acc);
            acc = fmaf(a4, sw[4 * 5 + c], acc);
            g_E32[o + c] = h2u(__float2half2_rn(fmaxf(acc, 0.0f)));  // duplicated
        }
    }
}

// ---------------------------------------------------------------------------
// K_proj: H=0 -> packed fp16 D (bias folded); H=1 -> packed fp16 S.
// 128x128 tile, 8x8 per thread.
// ---------------------------------------------------------------------------
__global__ __launch_bounds__(256) void k_proj(const float* __restrict__ wf,
                                              const float* __restrict__ ws,
                                              const float* __restrict__ bf,
                                              const float* __restrict__ bs) {
    __shared__ float Xs[32 * 129];
    __shared__ float Wsm[32 * 128];
    const int t = threadIdx.x;
    const int tx = t & 15, ty = t >> 4;
    const int H = blockIdx.y;
    const int base = blockIdx.x * 128;

    float acc[8][8];
#pragma unroll
    for (int i = 0; i < 8; i++)
#pragma unroll
        for (int j = 0; j < 8; j++) acc[i][j] = 0.0f;

    for (int ks = 0; ks < 64; ks += 32) {
        __syncthreads();
#pragma unroll
        for (int r = 0; r < 16; r++) {
            int idx = t + 256 * r;
            int n = idx >> 5;
            int k = idx & 31;
            int gn = base + n;
            Xs[k * 129 + n] = (gn < NN) ? g_X[(size_t)gn * 64 + ks + k] : 0.0f;
        }
#pragma unroll
        for (int r = 0; r < 16; r++) {
            int idx = t + 256 * r;
            int k = idx >> 7;
            int c = idx & 127;
            int grow = H * 64 + ks + k;
            Wsm[k * 128 + c] = (c < 64) ? wf[grow * 64 + c] : ws[grow * 64 + (c - 64)];
        }
        __syncthreads();
#pragma unroll
        for (int k = 0; k < 32; k++) {
            float xr[8], wr[8];
#pragma unroll
            for (int i = 0; i < 8; i++) xr[i] = Xs[k * 129 + i * 16 + ty];
#pragma unroll
            for (int j = 0; j < 8; j++) wr[j] = Wsm[k * 128 + j * 16 + tx];
#pragma unroll
            for (int i = 0; i < 8; i++)
#pragma unroll
                for (int j = 0; j < 8; j++)
                    acc[i][j] = fmaf(xr[i], wr[j], acc[i][j]);
        }
    }

    __half* outp = reinterpret_cast<__half*>(H == 0 ? g_Dpk : g_Spk);
#pragma unroll
    for (int i = 0; i < 8; i++) {
        int n = base + i * 16 + ty;
        if (n >= NN) continue;
#pragma unroll
        for (int j = 0; j < 8; j++) {
            int c = j * 16 + tx;
            float v = acc[i][j];
            if (H == 0) v += (c < 64) ? bf[c] : bs[c - 64];
            int cc = (c < 64) ? c : c - 64;
            int posh = 4 * (cc >> 1) + ((c < 64) ? 0 : 2) + (cc & 1);
            outp[(size_t)n * 128 + posh] = __float2half(v);
        }
    }
}

// ---------------------------------------------------------------------------
// K_edge_csr: one WARP per dst node; lane l owns channels 2l,2l+1 as half2.
// Per edge: 1 srcp bcast + 2 E bcast + 1 S LDG.64; z via HADD2+5xHFMA2 (x2);
// sigmoid via tanh.approx.f16x2; softplus fp32. Fused residual+relu epilogue.
// ---------------------------------------------------------------------------
__global__ __launch_bounds__(256) void k_edge_csr(const float* __restrict__ wef,
                                                  const float* __restrict__ wes,
                                                  float* __restrict__ out,
                                                  int final_) {
    int gw = (blockIdx.x * 256 + threadIdx.x) >> 5;
    int l = threadIdx.x & 31;
    if (gw >= NN) return;
    const int n = gw;

    __half2 wf2[5], ws2[5];
#pragma unroll
    for (int k = 0; k < 5; k++) {
        wf2[k] = __floats2half2_rn(wef[k * 64 + 2 * l], wef[k * 64 + 2 * l + 1]);
        ws2[k] = __floats2half2_rn(wes[k * 64 + 2 * l], wes[k * 64 + 2 * l + 1]);
    }
    const __half2 cHalf = __float2half2_rn(0.5f);

    uint2 dw = g_Dpk[(size_t)n * 32 + l];
    const __half2 Df2 = u2h(dw.x);
    const __half2 Ds2 = u2h(dw.y);

    float m0 = 0.0f, m1 = 0.0f;
    const int beg = __ldg(&g_off[n]), end = __ldg(&g_off[n + 1]);

#pragma unroll 2
    for (int k = beg; k < end; k++) {
        int s = __ldg(&g_srcp[k]);                                  // bcast
        uint4 ew = *reinterpret_cast<const uint4*>(&g_E32[(size_t)k * 8]);
        unsigned e4w = g_E32[(size_t)k * 8 + 4];
        uint2 sp_ = __ldg(&g_Spk[(size_t)s * 32 + l]);              // gather 8B

        __half2 zf = __hadd2(Df2, u2h(sp_.x));
        zf = __hfma2(u2h(ew.x), wf2[0], zf);
        zf = __hfma2(u2h(ew.y), wf2[1], zf);
        zf = __hfma2(u2h(ew.z), wf2[2], zf);
        zf = __hfma2(u2h(ew.w), wf2[3], zf);
        zf = __hfma2(u2h(e4w), wf2[4], zf);

        __half2 zs = __hadd2(Ds2, u2h(sp_.y));
        zs = __hfma2(u2h(ew.x), ws2[0], zs);
        zs = __hfma2(u2h(ew.y), ws2[1], zs);
        zs = __hfma2(u2h(ew.z), ws2[2], zs);
        zs = __hfma2(u2h(ew.w), ws2[3], zs);
        zs = __hfma2(u2h(e4w), ws2[4], zs);

        // gate = sigmoid(zf) via f16x2 tanh
        __half2 g2 = __hfma2(tanh_h2(__hmul2(zf, cHalf)), cHalf, cHalf);
        float2 gf = __half22float2(g2);
        float2 zsf = __half22float2(zs);

        m0 = fmaf(gf.x, softplus_f(zsf.x), m0);
        m1 = fmaf(gf.y, softplus_f(zsf.y), m1);
    }

    float2 x = *reinterpret_cast<const float2*>(g_X + (size_t)n * 64 + 2 * l);
    float2 r = make_float2(fmaxf(x.x + m0, 0.0f), fmaxf(x.y + m1, 0.0f));
    if (final_) {
        *reinterpret_cast<float2*>(out + (size_t)n * 64 + 2 * l) = r;
    } else {
        *reinterpret_cast<float2*>(g_X + (size_t)n * 64 + 2 * l) = r;
    }
}

// ---------------------------------------------------------------------------
// Launch. Inputs: h, edge_index, edge_weight, edge_attr, data,
// lin0_w, lin0_b, short_w, short_b, conv_f_w, conv_f_b, conv_s_w, conv_s_b
// Launch order puts first k_edge_csr at position 6 (ncu -s 5 -c 1 target).
// ---------------------------------------------------------------------------
extern "C" void kernel_launch(void* const* d_in, const int* in_sizes, int n_in,
                              void* d_out, int out_size) {
    int o = (n_in >= 13) ? 0 : -1;

    const float* h = (const float*)d_in[0];
    const int* ei = (const int*)d_in[1];  // int32 [2, NE]
    const float* ea = (const float*)d_in[3];
    const float* lin0_w = (const float*)d_in[5 + o];
    const float* lin0_b = (const float*)d_in[6 + o];
    const float* short_w = (const float*)d_in[7 + o];
    const float* short_b = (const float*)d_in[8 + o];
    const float* cfw = (const float*)d_in[9 + o];   // [2,133,64]
    const float* cfb = (const float*)d_in[10 + o];  // [2,64]
    const float* csw = (const float*)d_in[11 + o];
    const float* csb = (const float*)d_in[12 + o];
    float* out = (float*)d_out;

    const int EB = (NE + 255) / 256;

    k_hist<<<EB, 256>>>(ei);        // 1  (g_deg zero by static init / scatter drain)
    k_scan<<<1, 1024>>>();          // 2
    k_scatter<<<EB, 256>>>(ei);     // 3
    k_prep<<<LB + EBF, 256>>>(h, lin0_w, lin0_b, ea, short_w, short_b);  // 4

    for (int i = 0; i < 2; i++) {
        const float* wf = cfw + (size_t)i * 133 * 64;
        const float* ws = csw + (size_t)i * 133 * 64;
        dim3 pg((NN + 127) / 128, 2);
        k_proj<<<pg, 256>>>(wf, ws, cfb + i * 64, csb + i * 64);         // 5 / 7
        k_edge_csr<<<(NN * 32 + 255) / 256, 256>>>(wf + 128 * 64, ws + 128 * 64,
                                                   out, i == 1 ? 1 : 0); // 6 / 8
    }
}